// round 6
// baseline (speedup 1.0000x reference)
#include <cuda_runtime.h>
#include <cstdint>

// x (512,1,64,64) f32, weights (4,4,3) f32 -> out (512,12,31,31) f32
#define B_   512
#define H_   64
#define W_   64
#define HO_  31
#define WO_  31
#define NK_  4
#define LL_  (HO_ * WO_)          // 961 patches per batch image
#define TOTAL_ (B_ * LL_)         // 492032 = 3844 * 128 exactly

__device__ __forceinline__ float frcp_approx(float x) {
    float r;
    asm("rcp.approx.f32 %0, %1;" : "=f"(r) : "f"(x));
    return r;
}
__device__ __forceinline__ void stg_cs(float* p, float v) {
    asm volatile("st.global.cs.f32 [%0], %1;" :: "l"(p), "f"(v));
}

__global__ __launch_bounds__(128) void qconv_kernel(const float* __restrict__ x,
                                                    const float* __restrict__ w,
                                                    float* __restrict__ out) {
    // Fused coefficients (reduced-density-matrix algebra: only weights[k][0]
    // = (theta,phi,omega) reach the observables). e_a = alpha_a*d + beta_a*cc.
    // Fast trig: angles are O(0.01); __sincosf error ~1e-6 << 1e-3 budget.
    __shared__ float sc[24];
    if (threadIdx.x < NK_) {
        int k = threadIdx.x;
        float th = w[k * 12 + 0];
        float ph = w[k * 12 + 1];
        float om = w[k * 12 + 2];
        float st, ct, sp, cp, spo, cpo, smo, cmo;
        __sincosf(th, &st, &ct);
        __sincosf(ph, &sp, &cp);
        __sincosf(ph + om, &spo, &cpo);
        __sincosf(om - ph, &smo, &cmo);
        float c2 = 0.5f * (1.0f + ct);   // cos^2(th/2)
        float s2 = 0.5f * (1.0f - ct);   // sin^2(th/2)
        float so, co;
        __sincosf(om, &so, &co);
        sc[k * 6 + 0] = st * cp;
        sc[k * 6 + 1] = 2.0f * (c2 * cpo - s2 * cmo);
        sc[k * 6 + 2] = st * sp;
        sc[k * 6 + 3] = 2.0f * (c2 * spo + s2 * smo);
        sc[k * 6 + 4] = ct;
        sc[k * 6 + 5] = -2.0f * st * co;
    }
    __syncthreads();

    int tid = blockIdx.x * blockDim.x + threadIdx.x;   // grid exact: no bounds check
    int L  = tid % LL_;            // oh*31 + ow : directly the per-channel out offset
    int b  = tid / LL_;
    int oh = L / WO_;
    int ow = L - oh * WO_;

    const float* p = x + ((size_t)(b * H_ + oh * 2) * W_ + ow * 2);

    // 8 independent LDG.64 issued up front (max MLP)
    float2 a0 = *reinterpret_cast<const float2*>(p);
    float2 b0 = *reinterpret_cast<const float2*>(p + 2);
    float2 a1 = *reinterpret_cast<const float2*>(p + W_);
    float2 b1 = *reinterpret_cast<const float2*>(p + W_ + 2);
    float2 a2 = *reinterpret_cast<const float2*>(p + 2 * W_);
    float2 b2 = *reinterpret_cast<const float2*>(p + 2 * W_ + 2);
    float2 a3 = *reinterpret_cast<const float2*>(p + 3 * W_);
    float2 b3 = *reinterpret_cast<const float2*>(p + 3 * W_ + 2);

    // CNOT-ring folded to index algebra. Per column c (column sign +,-,-,+):
    //   A_c = v0^2 + v2^2, B_c = v1^2 + v3^2  (rows with MSB 0 / 1 after ring)
    //   C_c = v0*v3 + v1*v2                   (off-diagonal partner i ^ 12)
    float A0 = fmaf(a2.x, a2.x, a0.x * a0.x), B0 = fmaf(a3.x, a3.x, a1.x * a1.x);
    float A1 = fmaf(a2.y, a2.y, a0.y * a0.y), B1 = fmaf(a3.y, a3.y, a1.y * a1.y);
    float A2 = fmaf(b2.x, b2.x, b0.x * b0.x), B2 = fmaf(b3.x, b3.x, b1.x * b1.x);
    float A3 = fmaf(b2.y, b2.y, b0.y * b0.y), B3 = fmaf(b3.y, b3.y, b1.y * b1.y);

    float C0 = fmaf(a0.x, a3.x, a1.x * a2.x);
    float C1 = fmaf(a0.y, a3.y, a1.y * a2.y);
    float C2 = fmaf(b0.x, b3.x, b1.x * b2.x);
    float C3 = fmaf(b0.y, b3.y, b1.y * b2.y);

    float nrm = ((A0 + B0) + (A1 + B1)) + ((A2 + B2) + (A3 + B3));
    float d   = ((A0 - B0) - (A1 - B1)) - ((A2 - B2) - (A3 - B3));
    float cc  = (C0 + C1) + (C2 + C3);

    float inv = frcp_approx(fmaxf(nrm, 1e-30f));
    d  *= inv;
    cc *= inv;

    // out[b, ch, :] plane offset = b*12*961 + ch*961 + L ; coalesced per channel.
    float* o = out + (size_t)b * (12 * LL_) + L;
#pragma unroll
    for (int ch = 0; ch < 12; ch++) {
        stg_cs(o + (size_t)ch * LL_, fmaf(sc[2 * ch], d, sc[2 * ch + 1] * cc));
    }
}

extern "C" void kernel_launch(void* const* d_in, const int* in_sizes, int n_in,
                              void* d_out, int out_size) {
    const float* x = (const float*)d_in[0];
    const float* w = (const float*)d_in[1];
    if (n_in >= 2 && in_sizes[0] == NK_ * 4 * 3) {  // defensive input-order swap
        x = (const float*)d_in[1];
        w = (const float*)d_in[0];
    }
    qconv_kernel<<<TOTAL_ / 128, 128>>>(x, w, (float*)d_out);
}

// round 8
// speedup vs baseline: 1.0364x; 1.0364x over previous
#include <cuda_runtime.h>
#include <cstdint>

// x (512,1,64,64) f32, weights (4,4,3) f32 -> out (512,12,31,31) f32
#define B_    512
#define H_    64
#define W_    64
#define HO_   31
#define WO_   31
#define NK_   4
#define LL_   (HO_ * WO_)            // 961
#define NWARP_ (B_ * HO_)            // 15872 warps, one per (b, oh)
#define WPB_   8                     // 256-thread blocks
#define NBLK_  (NWARP_ / WPB_)       // 1984 exact

#define TSTRIDE_ 68                  // smem row stride (floats): 17*16B, pad kills conflicts

__device__ __forceinline__ float frcp_approx(float x) {
    float r;
    asm("rcp.approx.f32 %0, %1;" : "=f"(r) : "f"(x));
    return r;
}

__global__ __launch_bounds__(256) void qconv_kernel(const float* __restrict__ x,
                                                    const float* __restrict__ w,
                                                    float* __restrict__ out) {
    // Coefs: reduced-density-matrix algebra — only weights[k][0]=(th,ph,om) matter.
    // e_a = alpha_a * d + beta_a * cc. Stored interleaved as float2 pairs.
    __shared__ float2 sc2[12];
    __shared__ float tile[WPB_][4][TSTRIDE_];

    if (threadIdx.x < NK_) {
        int k = threadIdx.x;
        float th = w[k * 12 + 0];
        float ph = w[k * 12 + 1];
        float om = w[k * 12 + 2];
        float st, ct, sp, cp, spo, cpo, smo, cmo, so, co;
        __sincosf(th, &st, &ct);
        __sincosf(ph, &sp, &cp);
        __sincosf(ph + om, &spo, &cpo);
        __sincosf(om - ph, &smo, &cmo);
        __sincosf(om, &so, &co);
        float c2 = 0.5f * (1.0f + ct);
        float s2 = 0.5f * (1.0f - ct);
        sc2[k * 3 + 0] = make_float2(st * cp, 2.0f * (c2 * cpo - s2 * cmo));
        sc2[k * 3 + 1] = make_float2(st * sp, 2.0f * (c2 * spo + s2 * smo));
        sc2[k * 3 + 2] = make_float2(ct, -2.0f * st * co);
    }
    __syncthreads();

    int wslot = threadIdx.x >> 5;
    int lane  = threadIdx.x & 31;
    int Wg    = blockIdx.x * WPB_ + wslot;   // global warp id = (b, oh)
    int b  = Wg / HO_;
    int oh = Wg - b * HO_;

    // Warp cooperative load: 4 rows x 64 cols strip, every float loaded once.
    // 2 LDG.128 per lane, fully coalesced (16 lanes per row).
    const float* base = x + (size_t)(b * H_ + 2 * oh) * W_;
#pragma unroll
    for (int j = 0; j < 2; j++) {
        int idx = lane + 32 * j;             // 0..63
        int r   = idx >> 4;
        int c4  = idx & 15;
        float4 v = *reinterpret_cast<const float4*>(base + r * W_ + c4 * 4);
        *reinterpret_cast<float4*>(&tile[wslot][r][c4 * 4]) = v;
    }
    __syncwarp();

    if (lane < WO_) {
        // Window for patch ow=lane: rows 0..3, cols 2*lane .. 2*lane+3
        float2 a0 = *reinterpret_cast<const float2*>(&tile[wslot][0][2 * lane]);
        float2 b0 = *reinterpret_cast<const float2*>(&tile[wslot][0][2 * lane + 2]);
        float2 a1 = *reinterpret_cast<const float2*>(&tile[wslot][1][2 * lane]);
        float2 b1 = *reinterpret_cast<const float2*>(&tile[wslot][1][2 * lane + 2]);
        float2 a2 = *reinterpret_cast<const float2*>(&tile[wslot][2][2 * lane]);
        float2 b2 = *reinterpret_cast<const float2*>(&tile[wslot][2][2 * lane + 2]);
        float2 a3 = *reinterpret_cast<const float2*>(&tile[wslot][3][2 * lane]);
        float2 b3 = *reinterpret_cast<const float2*>(&tile[wslot][3][2 * lane + 2]);

        // CNOT-ring folded to index algebra (column signs +,-,-,+):
        //   A_c = v0^2+v2^2, B_c = v1^2+v3^2, C_c = v0*v3 + v1*v2 (partner i^12)
        float A0 = fmaf(a2.x, a2.x, a0.x * a0.x), B0 = fmaf(a3.x, a3.x, a1.x * a1.x);
        float A1 = fmaf(a2.y, a2.y, a0.y * a0.y), B1 = fmaf(a3.y, a3.y, a1.y * a1.y);
        float A2 = fmaf(b2.x, b2.x, b0.x * b0.x), B2 = fmaf(b3.x, b3.x, b1.x * b1.x);
        float A3 = fmaf(b2.y, b2.y, b0.y * b0.y), B3 = fmaf(b3.y, b3.y, b1.y * b1.y);

        float C0 = fmaf(a0.x, a3.x, a1.x * a2.x);
        float C1 = fmaf(a0.y, a3.y, a1.y * a2.y);
        float C2 = fmaf(b0.x, b3.x, b1.x * b2.x);
        float C3 = fmaf(b0.y, b3.y, b1.y * b2.y);

        float nrm = ((A0 + B0) + (A1 + B1)) + ((A2 + B2) + (A3 + B3));
        float d   = ((A0 - B0) - (A1 - B1)) - ((A2 - B2) - (A3 - B3));
        float cc  = (C0 + C1) + (C2 + C3);

        float inv = frcp_approx(fmaxf(nrm, 1e-30f));
        d  *= inv;
        cc *= inv;

        // out[b, ch, oh, ow]; lanes 0..30 -> 31 consecutive floats per channel
        float* o = out + (size_t)b * (12 * LL_) + oh * WO_ + lane;
#pragma unroll
        for (int ch = 0; ch < 12; ch++) {
            float2 ab = sc2[ch];
            o[(size_t)ch * LL_] = fmaf(ab.x, d, ab.y * cc);
        }
    }
}

extern "C" void kernel_launch(void* const* d_in, const int* in_sizes, int n_in,
                              void* d_out, int out_size) {
    const float* x = (const float*)d_in[0];
    const float* w = (const float*)d_in[1];
    if (n_in >= 2 && in_sizes[0] == NK_ * 4 * 3) {  // defensive input-order swap
        x = (const float*)d_in[1];
        w = (const float*)d_in[0];
    }
    qconv_kernel<<<NBLK_, 256>>>(x, w, (float*)d_out);
}